// round 11
// baseline (speedup 1.0000x reference)
#include <cuda_runtime.h>

#define KK    15
#define PADK  7
#define TW    128
#define TH    64
#define TROWS (TH + 2 * PADK)   // 78
#define HH    512
#define WW    512
#define CH    3

__global__ __launch_bounds__(256, 5)   // 5 blocks/SM (also the 40KB-smem ceiling)
void gauss_blur_kernel(const float* __restrict__ xin_all,
                       const float* __restrict__ sigma,
                       float* __restrict__ out_all)
{
    __shared__ __align__(16) float temp[TROWS][TW];   // 39936 B
    __shared__ float wsh[KK];

    const int bc = blockIdx.z;          // b * C + c
    const int b  = bc / CH;

    // --- per-batch separable weights: w_i = g_i / sqrt(S^2 + 1e-8) ---
    if (threadIdx.x == 0) {
        float s  = sigma[b];
        float s2 = 2.0f * s * s + 1e-8f;
        float g[KK];
        float S = 0.0f;
        #pragma unroll
        for (int i = 0; i < KK; i++) {
            float d = (float)(i - PADK);
            g[i] = expf(-(d * d) / s2);
            S += g[i];
        }
        float inv = rsqrtf(S * S + 1e-8f);
        #pragma unroll
        for (int i = 0; i < KK; i++) wsh[i] = g[i] * inv;
    }
    __syncthreads();

    const float* __restrict__ img    = xin_all + (size_t)bc * HH * WW;
    float*       __restrict__ outimg = out_all + (size_t)bc * HH * WW;
    const int y0 = blockIdx.y * TH;
    const int x0 = blockIdx.x * TW;

    // ---------------- Phase 1: horizontal conv into shared ----------------
    // 8 x-groups of 16 outputs x 32 row-lanes. One 32-float window (8x float4)
    // feeds 16 outputs, but loads are STAGED: f4[0..5] -> compute outputs 0..7
    // -> f4[6..7] -> compute outputs 8..15. Peak live ~32 floats (no spill).
    {
        const int xg   = threadIdx.x & 7;
        const int ry   = threadIdx.x >> 3;       // 32 row-lanes
        const int gx0a = x0 + xg * 16 - 8;       // 32B-aligned window start

        for (int r = ry; r < TROWS; r += 32) {
            const int gy = y0 - PADK + r;
            const bool rowok = (unsigned)gy < (unsigned)HH;
            const float* row = img + (size_t)gy * WW;

            float in[32];
            // Stage A: first six float4 (in[0..23])
            #pragma unroll
            for (int v = 0; v < 6; v++) {
                const int gxv = gx0a + v * 4;
                if (rowok && (unsigned)gxv <= (unsigned)(WW - 4)) {
                    float4 t = *reinterpret_cast<const float4*>(row + gxv);
                    in[v * 4 + 0] = t.x; in[v * 4 + 1] = t.y;
                    in[v * 4 + 2] = t.z; in[v * 4 + 3] = t.w;
                } else {
                    #pragma unroll
                    for (int e = 0; e < 4; e++) {
                        int gx = gxv + e;
                        in[v * 4 + e] = (rowok && (unsigned)gx < (unsigned)WW) ? row[gx] : 0.0f;
                    }
                }
            }

            // Batch A: outputs 0..7 from in[1..22]
            {
                float acc[8];
                #pragma unroll
                for (int j = 0; j < 8; j++) acc[j] = 0.0f;
                #pragma unroll
                for (int k = 0; k < KK; k++) {
                    const float wk = wsh[k];
                    #pragma unroll
                    for (int j = 0; j < 8; j++)
                        acc[j] = fmaf(wk, in[1 + j + k], acc[j]);
                }
                float4* dst = reinterpret_cast<float4*>(&temp[r][xg * 16]);
                dst[0] = make_float4(acc[0], acc[1], acc[2], acc[3]);
                dst[1] = make_float4(acc[4], acc[5], acc[6], acc[7]);
            }

            // Stage B: last two float4 (in[24..31]); in[0..8] are dead now
            #pragma unroll
            for (int v = 6; v < 8; v++) {
                const int gxv = gx0a + v * 4;
                if (rowok && (unsigned)gxv <= (unsigned)(WW - 4)) {
                    float4 t = *reinterpret_cast<const float4*>(row + gxv);
                    in[v * 4 + 0] = t.x; in[v * 4 + 1] = t.y;
                    in[v * 4 + 2] = t.z; in[v * 4 + 3] = t.w;
                } else {
                    #pragma unroll
                    for (int e = 0; e < 4; e++) {
                        int gx = gxv + e;
                        in[v * 4 + e] = (rowok && (unsigned)gx < (unsigned)WW) ? row[gx] : 0.0f;
                    }
                }
            }

            // Batch B: outputs 8..15 from in[9..30]
            {
                float acc[8];
                #pragma unroll
                for (int j = 0; j < 8; j++) acc[j] = 0.0f;
                #pragma unroll
                for (int k = 0; k < KK; k++) {
                    const float wk = wsh[k];
                    #pragma unroll
                    for (int j = 0; j < 8; j++)
                        acc[j] = fmaf(wk, in[9 + j + k], acc[j]);
                }
                float4* dst = reinterpret_cast<float4*>(&temp[r][xg * 16 + 8]);
                dst[0] = make_float4(acc[0], acc[1], acc[2], acc[3]);
                dst[1] = make_float4(acc[4], acc[5], acc[6], acc[7]);
            }
        }
    }
    __syncthreads();

    // ---------------- Phase 2: vertical conv with register sliding window ----------------
    // (R5 proven shape) 128 columns x 2 vertical halves of 32 rows.
    // 46 scalar LDS per 32 outputs; conflict-free; coalesced scalar STG.
    {
        const int col   = threadIdx.x & 127;
        const int half  = threadIdx.x >> 7;      // 0 or 1
        const int ybase = half * 32;

        float wl[KK];
        #pragma unroll
        for (int i = 0; i < KK; i++) wl[i] = wsh[i];

        float win[KK];                            // ring, constant-indexed after unroll
        #pragma unroll
        for (int i = 0; i < KK; i++) win[i] = temp[ybase + i][col];

        float* ocol = outimg + (size_t)(y0 + ybase) * WW + x0 + col;

        #pragma unroll
        for (int j = 0; j < 32; j++) {
            float a = 0.0f;
            #pragma unroll
            for (int k = 0; k < KK; k++)
                a = fmaf(wl[k], win[(j + k) % KK], a);
            ocol[(size_t)j * WW] = a;
            if (j < 31)
                win[j % KK] = temp[ybase + j + KK][col];
        }
    }
}

extern "C" void kernel_launch(void* const* d_in, const int* in_sizes, int n_in,
                              void* d_out, int out_size)
{
    const float* x     = (const float*)d_in[0];
    const float* sigma = (const float*)d_in[1];
    float*       out   = (float*)d_out;

    const int B = in_sizes[1];                 // sigma has one entry per batch
    dim3 grid(WW / TW, HH / TH, B * CH);       // (4, 8, 96)
    gauss_blur_kernel<<<grid, 256>>>(x, sigma, out);
}

// round 12
// speedup vs baseline: 1.2920x; 1.2920x over previous
#include <cuda_runtime.h>

#define KK    15
#define PADK  7
#define TW    128
#define TH    64
#define TROWS (TH + 2 * PADK)   // 78
#define HH    512
#define WW    512
#define CH    3

__global__ __launch_bounds__(256, 5)
void gauss_blur_kernel(const float* __restrict__ xin_all,
                       const float* __restrict__ sigma,
                       float* __restrict__ out_all)
{
    __shared__ __align__(16) float temp[TROWS][TW];   // 39936 B
    __shared__ float wsh[KK];

    const int bc = blockIdx.z;          // b * C + c
    const int b  = bc / CH;

    // --- per-batch separable weights: w_i = g_i / sqrt(S^2 + 1e-8) ---
    if (threadIdx.x == 0) {
        float s  = sigma[b];
        float s2 = 2.0f * s * s + 1e-8f;
        float g[KK];
        float S = 0.0f;
        #pragma unroll
        for (int i = 0; i < KK; i++) {
            float d = (float)(i - PADK);
            g[i] = expf(-(d * d) / s2);
            S += g[i];
        }
        float inv = rsqrtf(S * S + 1e-8f);
        #pragma unroll
        for (int i = 0; i < KK; i++) wsh[i] = g[i] * inv;
    }
    __syncthreads();

    float wl[KK];
    #pragma unroll
    for (int i = 0; i < KK; i++) wl[i] = wsh[i];

    const float* __restrict__ img    = xin_all + (size_t)bc * HH * WW;
    float*       __restrict__ outimg = out_all + (size_t)bc * HH * WW;
    const int y0 = blockIdx.y * TH;
    const int x0 = blockIdx.x * TW;

    // ---------------- Phase 1: horizontal conv into shared (R5 shape) ----------------
    // 16 x-groups of 8 outputs x 16 row-lanes. Aligned 24-float window via 6x float4.
    // unroll 2: overlap next iteration's LDG batch with current FFMA tail (MLP).
    {
        const int xg   = threadIdx.x & 15;
        const int ry   = threadIdx.x >> 4;
        const int gx0a = x0 + xg * 8 - 8;        // 32B-aligned window start

        #pragma unroll 2
        for (int r = ry; r < TROWS; r += 16) {
            const int gy = y0 - PADK + r;
            float in[24];
            if ((unsigned)gy < (unsigned)HH) {
                const float* row = img + (size_t)gy * WW;
                #pragma unroll
                for (int v = 0; v < 6; v++) {
                    const int gxv = gx0a + v * 4;
                    if ((unsigned)gxv <= (unsigned)(WW - 4)) {
                        float4 t = *reinterpret_cast<const float4*>(row + gxv);
                        in[v * 4 + 0] = t.x; in[v * 4 + 1] = t.y;
                        in[v * 4 + 2] = t.z; in[v * 4 + 3] = t.w;
                    } else {
                        #pragma unroll
                        for (int e = 0; e < 4; e++) {
                            int gx = gxv + e;
                            in[v * 4 + e] = ((unsigned)gx < (unsigned)WW) ? row[gx] : 0.0f;
                        }
                    }
                }
            } else {
                #pragma unroll
                for (int i = 0; i < 24; i++) in[i] = 0.0f;
            }

            float acc[8];
            #pragma unroll
            for (int j = 0; j < 8; j++) {
                float a = 0.0f;
                #pragma unroll
                for (int k = 0; k < KK; k++)
                    a = fmaf(wl[k], in[1 + j + k], a);
                acc[j] = a;
            }

            float4* dst = reinterpret_cast<float4*>(&temp[r][xg * 8]);
            dst[0] = make_float4(acc[0], acc[1], acc[2], acc[3]);
            dst[1] = make_float4(acc[4], acc[5], acc[6], acc[7]);
        }
    }
    __syncthreads();

    // ---------------- Phase 2: vertical conv with register sliding window ----------------
    // 128 columns x 2 vertical halves of 32 rows. Dual accumulators cut the
    // per-output dependency chain from 15 FFMAs to 8.
    {
        const int col   = threadIdx.x & 127;
        const int half  = threadIdx.x >> 7;      // 0 or 1
        const int ybase = half * 32;

        float win[KK];                            // ring, constant-indexed after unroll
        #pragma unroll
        for (int i = 0; i < KK; i++) win[i] = temp[ybase + i][col];

        float* ocol = outimg + (size_t)(y0 + ybase) * WW + x0 + col;

        #pragma unroll
        for (int j = 0; j < 32; j++) {
            float a0 = 0.0f, a1 = 0.0f;
            #pragma unroll
            for (int k = 0; k < 8; k++)
                a0 = fmaf(wl[k], win[(j + k) % KK], a0);
            #pragma unroll
            for (int k = 8; k < KK; k++)
                a1 = fmaf(wl[k], win[(j + k) % KK], a1);
            ocol[(size_t)j * WW] = a0 + a1;
            if (j < 31)
                win[j % KK] = temp[ybase + j + KK][col];
        }
    }
}

extern "C" void kernel_launch(void* const* d_in, const int* in_sizes, int n_in,
                              void* d_out, int out_size)
{
    const float* x     = (const float*)d_in[0];
    const float* sigma = (const float*)d_in[1];
    float*       out   = (float*)d_out;

    const int B = in_sizes[1];                 // sigma has one entry per batch
    dim3 grid(WW / TW, HH / TH, B * CH);       // (4, 8, 96)
    gauss_blur_kernel<<<grid, 256>>>(x, sigma, out);
}

// round 15
// speedup vs baseline: 1.4928x; 1.1554x over previous
#include <cuda_runtime.h>
#include <cuda_fp16.h>

#define KK    15
#define PADK  7
#define TW    128
#define TH    128
#define TROWS (TH + 2 * PADK)   // 142
#define HH    512
#define WW    512
#define CH    3

struct __align__(16) Half8 { __half2 a, b, c, d; };

__global__ __launch_bounds__(256, 5)
void gauss_blur_kernel(const float* __restrict__ xin_all,
                       const float* __restrict__ sigma,
                       float* __restrict__ out_all)
{
    __shared__ __align__(16) __half temp[TROWS][TW];  // 142*128*2 = 36352 B
    __shared__ float wsh[KK];

    const int bc = blockIdx.z;          // b * C + c
    const int b  = bc / CH;

    // --- per-batch separable weights: w_i = g_i / sqrt(S^2 + 1e-8) ---
    if (threadIdx.x == 0) {
        float s  = sigma[b];
        float s2 = 2.0f * s * s + 1e-8f;
        float g[KK];
        float S = 0.0f;
        #pragma unroll
        for (int i = 0; i < KK; i++) {
            float d = (float)(i - PADK);
            g[i] = expf(-(d * d) / s2);
            S += g[i];
        }
        float inv = rsqrtf(S * S + 1e-8f);
        #pragma unroll
        for (int i = 0; i < KK; i++) wsh[i] = g[i] * inv;
    }
    __syncthreads();

    float wl[KK];
    #pragma unroll
    for (int i = 0; i < KK; i++) wl[i] = wsh[i];

    const float* __restrict__ img    = xin_all + (size_t)bc * HH * WW;
    float*       __restrict__ outimg = out_all + (size_t)bc * HH * WW;
    const int y0 = blockIdx.y * TH;
    const int x0 = blockIdx.x * TW;

    // ---------------- Phase 1: horizontal conv into shared (R5 inner shape) -------------
    // 16 x-groups of 8 outputs x 16 row-lanes, fp32 math, fp16 store (8 halves = STS.128).
    {
        const int xg   = threadIdx.x & 15;
        const int ry   = threadIdx.x >> 4;
        const int gx0a = x0 + xg * 8 - 8;        // 32B-aligned window start

        for (int r = ry; r < TROWS; r += 16) {
            const int gy = y0 - PADK + r;
            float in[24];
            if ((unsigned)gy < (unsigned)HH) {
                const float* row = img + (size_t)gy * WW;
                #pragma unroll
                for (int v = 0; v < 6; v++) {
                    const int gxv = gx0a + v * 4;
                    if ((unsigned)gxv <= (unsigned)(WW - 4)) {
                        float4 t = *reinterpret_cast<const float4*>(row + gxv);
                        in[v * 4 + 0] = t.x; in[v * 4 + 1] = t.y;
                        in[v * 4 + 2] = t.z; in[v * 4 + 3] = t.w;
                    } else {
                        #pragma unroll
                        for (int e = 0; e < 4; e++) {
                            int gx = gxv + e;
                            in[v * 4 + e] = ((unsigned)gx < (unsigned)WW) ? row[gx] : 0.0f;
                        }
                    }
                }
            } else {
                #pragma unroll
                for (int i = 0; i < 24; i++) in[i] = 0.0f;
            }

            float acc[8];
            #pragma unroll
            for (int j = 0; j < 8; j++) {
                float a = 0.0f;
                #pragma unroll
                for (int k = 0; k < KK; k++)
                    a = fmaf(wl[k], in[1 + j + k], a);
                acc[j] = a;
            }

            // pack 8 fp32 -> 8 fp16 -> one 16B store
            Half8 pk;
            pk.a = __floats2half2_rn(acc[0], acc[1]);
            pk.b = __floats2half2_rn(acc[2], acc[3]);
            pk.c = __floats2half2_rn(acc[4], acc[5]);
            pk.d = __floats2half2_rn(acc[6], acc[7]);
            *reinterpret_cast<Half8*>(&temp[r][xg * 8]) = pk;
        }
    }
    __syncthreads();

    // ---------------- Phase 2: vertical conv with register sliding window ----------------
    // 128 columns x 2 vertical halves of 64 rows. 78 scalar fp16 LDS per 64 outputs.
    // j-loop blocked 4x15+4 so ring indices stay compile-time constants.
    {
        const int col   = threadIdx.x & 127;
        const int half  = threadIdx.x >> 7;      // 0 or 1
        const int ybase = half * 64;

        float win[KK];                            // ring, constant-indexed
        #pragma unroll
        for (int i = 0; i < KK; i++) win[i] = __half2float(temp[ybase + i][col]);

        float* ocol = outimg + (size_t)(y0 + ybase) * WW + x0 + col;

        #pragma unroll 1
        for (int blk = 0; blk < 4; blk++) {       // outputs blk*15 + jj, jj=0..14
            const int jb = blk * 15;
            #pragma unroll
            for (int jj = 0; jj < 15; jj++) {
                float a = 0.0f;
                #pragma unroll
                for (int k = 0; k < KK; k++)
                    a = fmaf(wl[k], win[(jj + k) % KK], a);
                ocol[(size_t)(jb + jj) * WW] = a;
                // j = jb+jj <= 59 < 63, so next-row load always valid
                win[jj % KK] = __half2float(temp[ybase + jb + jj + KK][col]);
            }
        }
        // epilogue: outputs 60..63 (ring phase is back to 0 after 60 = 4*15)
        #pragma unroll
        for (int jj = 0; jj < 4; jj++) {
            float a = 0.0f;
            #pragma unroll
            for (int k = 0; k < KK; k++)
                a = fmaf(wl[k], win[(jj + k) % KK], a);
            ocol[(size_t)(60 + jj) * WW] = a;
            if (jj < 3)
                win[jj % KK] = __half2float(temp[ybase + 60 + jj + KK][col]);
        }
    }
}

extern "C" void kernel_launch(void* const* d_in, const int* in_sizes, int n_in,
                              void* d_out, int out_size)
{
    const float* x     = (const float*)d_in[0];
    const float* sigma = (const float*)d_in[1];
    float*       out   = (float*)d_out;

    const int B = in_sizes[1];                 // sigma has one entry per batch
    dim3 grid(WW / TW, HH / TH, B * CH);       // (4, 4, 96)
    gauss_blur_kernel<<<grid, 256>>>(x, sigma, out);
}